// round 5
// baseline (speedup 1.0000x reference)
#include <cuda_runtime.h>
#include <cuda_fp16.h>
#include <mma.h>
using namespace nvcuda;

// ---------------- problem constants ----------------
#define NN   50000
#define NE   1600000
#define NEP  (NE + NN)      // edges + self loops
#define KDIM 256
#define HC   128
#define NEG  0.2f

// ---------------- device scratch ----------------
__device__ __half g_Bcat_h[KDIM * 256];   // [k][j]: j<128 -> W_f, else W_b
__device__ __half g_Wfuse_h[KDIM * 256];
__device__ __half g_xl_f[NN * HC];
__device__ __half g_xl_b[NN * HC];
__device__ __half g_agg_h[NN * 256];      // concat(agg_f, agg_b) fp16
__device__ float g_al_f[NN * 4];
__device__ float g_ar_f[NN * 4];
__device__ float g_al_b[NN * 4];
__device__ float g_ar_b[NN * 4];
__device__ float g_scale[256];
__device__ float g_shift[256];
// CSR scratch (dir 0 = in, dir 1 = out)
__device__ int g_deg[2][NN];
__device__ int g_off[2][NN];
__device__ int g_cur[2][NN];
__device__ int g_adj[2][NEP];   // [0]: in-edges sorted by dst (stores src)
                                // [1]: out-edges sorted by src (stores dst)

__device__ __forceinline__ float lrelu(float v) { return v > 0.f ? v : NEG * v; }

// ---------------- prep ----------------
__global__ void pack_kernel(const float* __restrict__ b_fuse,
                            const float* __restrict__ gamma, const float* __restrict__ beta,
                            const float* __restrict__ mean, const float* __restrict__ var,
                            int dir) {
    int t = blockIdx.x * blockDim.x + threadIdx.x;
    if (t < NN) g_deg[dir][t] = 0;
    if (dir == 0 && t < 256) {
        float inv = rsqrtf(var[t] + 1e-5f);
        float sc = gamma[t] * inv;
        g_scale[t] = sc;
        g_shift[t] = beta[t] + (b_fuse[t] - mean[t]) * sc;
    }
}

__global__ void conv_w_kernel(const float* __restrict__ Wf, const float* __restrict__ Wb,
                              const float* __restrict__ Wfu) {
    int t = blockIdx.x * blockDim.x + threadIdx.x;
    if (t < KDIM * 256) {
        int k = t >> 8, j = t & 255;
        float v = (j < HC) ? Wf[k * HC + j] : Wb[k * HC + (j - HC)];
        g_Bcat_h[t] = __float2half_rn(v);
        g_Wfuse_h[t] = __float2half_rn(Wfu[t]);
    }
}

// ---------------- CSR build (per direction) ----------------
// dir 0: count/list keyed by dst, store src.  dir 1: keyed by src, store dst.
__global__ void hist_kernel(const int* __restrict__ ei, int dir) {
    int idx = blockIdx.x * blockDim.x + threadIdx.x;
    if (idx >= NEP) return;
    int key;
    if (idx < NE) key = __ldg(&ei[(dir ? 0 : 1) * NE + idx]);
    else          key = idx - NE;
    atomicAdd(&g_deg[dir][key], 1);
}

__global__ void scan_kernel(int dir) {
    __shared__ int part[1024];
    int* deg = g_deg[dir];
    int* off = g_off[dir];
    int* cur = g_cur[dir];
    int t = threadIdx.x;
    const int CH = (NN + 1023) / 1024;
    int base = t * CH;
    int s = 0;
    for (int i = 0; i < CH; i++) { int idx = base + i; if (idx < NN) s += deg[idx]; }
    part[t] = s;
    __syncthreads();
    for (int d = 1; d < 1024; d <<= 1) {
        int v = (t >= d) ? part[t - d] : 0;
        __syncthreads();
        part[t] += v;
        __syncthreads();
    }
    int pre = (t == 0) ? 0 : part[t - 1];
    for (int i = 0; i < CH; i++) {
        int idx = base + i;
        if (idx < NN) { off[idx] = pre; cur[idx] = pre; pre += deg[idx]; }
    }
}

__global__ void scatter_kernel(const int* __restrict__ ei, int dir) {
    int idx = blockIdx.x * blockDim.x + threadIdx.x;
    if (idx >= NEP) return;
    int key, val;
    if (idx < NE) {
        int s = __ldg(&ei[idx]);
        int d = __ldg(&ei[NE + idx]);
        key = dir ? s : d;
        val = dir ? d : s;
    } else {
        key = val = idx - NE;
    }
    int p = atomicAdd(&g_cur[dir][key], 1);
    g_adj[dir][p] = val;
}

// ---------------- HMMA GEMM: 128x128 tile, BK=32, 8 warps (4M x 2N) ----------------
// MODE 0: C = half(x) @ g_Bcat_h; blockIdx.y = direction -> xl fp16 + al/ar epilogue
//         (A tile converted fp32->fp16 on the fly from x)
// MODE 1: C = g_agg_h @ g_Wfuse_h -> BN+ReLU -> out
#define A_LDM 40
#define B_LDM 136
#define C_LDM 132
#define SMEM_SZ (128 * C_LDM * 4)

template <int MODE>
__global__ void __launch_bounds__(256)
hgemm_kernel(const float* __restrict__ Af32, float* __restrict__ Cout,
             const float* __restrict__ asrc_f, const float* __restrict__ adst_f,
             const float* __restrict__ asrc_b, const float* __restrict__ adst_b) {
    extern __shared__ char sm_raw[];
    __half* As = (__half*)sm_raw;                        // [128][A_LDM]
    __half* Bs = (__half*)(sm_raw + 128 * A_LDM * 2);    // [32][B_LDM]
    float* Cs = (float*)sm_raw;                          // [128][C_LDM] (after loop)

    const int tid = threadIdx.x;
    const int warp = tid >> 5;
    const int wm = warp & 3;
    const int wn = warp >> 2;
    const int row0 = blockIdx.x * 128;
    const int dir = blockIdx.y;
    const int colB = dir * 128;

    const __half* Bg = (MODE == 0) ? g_Bcat_h : g_Wfuse_h;

    wmma::fragment<wmma::accumulator, 16, 16, 16, float> acc[2][4];
#pragma unroll
    for (int i = 0; i < 2; i++)
#pragma unroll
        for (int j = 0; j < 4; j++) wmma::fill_fragment(acc[i][j], 0.f);

    for (int kt = 0; kt < KDIM; kt += 32) {
        // A tile: 128 rows x 32 cols (8-half chunks; 512 chunks / 256 thr = 2)
#pragma unroll
        for (int l = 0; l < 2; l++) {
            int c = tid + l * 256;
            int r = c >> 2;
            int c8 = (c & 3) * 8;
            int grow = row0 + r;
            uint4 pk = make_uint4(0, 0, 0, 0);
            if (grow < NN) {
                if (MODE == 0) {
                    const float* p = Af32 + (size_t)grow * KDIM + kt + c8;
                    float4 va = *(const float4*)p;
                    float4 vb = *(const float4*)(p + 4);
                    __half2 h0 = __floats2half2_rn(va.x, va.y);
                    __half2 h1 = __floats2half2_rn(va.z, va.w);
                    __half2 h2 = __floats2half2_rn(vb.x, vb.y);
                    __half2 h3 = __floats2half2_rn(vb.z, vb.w);
                    pk = make_uint4(*(unsigned*)&h0, *(unsigned*)&h1,
                                    *(unsigned*)&h2, *(unsigned*)&h3);
                } else {
                    pk = *(const uint4*)(g_agg_h + (size_t)grow * KDIM + kt + c8);
                }
            }
            *(uint4*)(As + r * A_LDM + c8) = pk;
        }
        // B tile: 32 rows x 128 cols
#pragma unroll
        for (int l = 0; l < 2; l++) {
            int c = tid + l * 256;
            int r = c >> 4;
            int c8 = (c & 15) * 8;
            *(uint4*)(Bs + r * B_LDM + c8) =
                *(const uint4*)(Bg + (size_t)(kt + r) * 256 + colB + c8);
        }
        __syncthreads();
#pragma unroll
        for (int kk = 0; kk < 32; kk += 16) {
            wmma::fragment<wmma::matrix_a, 16, 16, 16, __half, wmma::row_major> af[2];
            wmma::fragment<wmma::matrix_b, 16, 16, 16, __half, wmma::row_major> bf[4];
#pragma unroll
            for (int i = 0; i < 2; i++)
                wmma::load_matrix_sync(af[i], As + (wm * 32 + i * 16) * A_LDM + kk, A_LDM);
#pragma unroll
            for (int j = 0; j < 4; j++)
                wmma::load_matrix_sync(bf[j], Bs + kk * B_LDM + wn * 64 + j * 16, B_LDM);
#pragma unroll
            for (int i = 0; i < 2; i++)
#pragma unroll
                for (int j = 0; j < 4; j++)
                    wmma::mma_sync(acc[i][j], af[i], bf[j], acc[i][j]);
        }
        __syncthreads();
    }

#pragma unroll
    for (int i = 0; i < 2; i++)
#pragma unroll
        for (int j = 0; j < 4; j++)
            wmma::store_matrix_sync(Cs + (wm * 32 + i * 16) * C_LDM + wn * 64 + j * 16,
                                    acc[i][j], C_LDM, wmma::mem_row_major);
    __syncthreads();

    const int r = tid >> 1;
    const int c0 = (tid & 1) * 64;
    const int grow = row0 + r;
    if (grow >= NN) return;
    const float* Crow = Cs + r * C_LDM + c0;

    if (MODE == 0) {
        __half* xl = dir ? g_xl_b : g_xl_f;
        const float* asrc = dir ? asrc_b : asrc_f;
        const float* adst = dir ? adst_b : adst_f;
        float* alp = dir ? g_al_b : g_al_f;
        float* arp = dir ? g_ar_b : g_ar_f;
#pragma unroll
        for (int hh = 0; hh < 2; hh++) {
            int head = (tid & 1) * 2 + hh;
            float ps = 0.f, pd = 0.f;
#pragma unroll
            for (int c = 0; c < 32; c++) {
                float v = Crow[hh * 32 + c];
                ps = fmaf(v, __ldg(&asrc[head * 32 + c]), ps);
                pd = fmaf(v, __ldg(&adst[head * 32 + c]), pd);
            }
            alp[grow * 4 + head] = ps;
            arp[grow * 4 + head] = pd;
        }
#pragma unroll
        for (int c = 0; c < 64; c += 8) {
            __half2 h0 = __floats2half2_rn(Crow[c + 0], Crow[c + 1]);
            __half2 h1 = __floats2half2_rn(Crow[c + 2], Crow[c + 3]);
            __half2 h2 = __floats2half2_rn(Crow[c + 4], Crow[c + 5]);
            __half2 h3 = __floats2half2_rn(Crow[c + 6], Crow[c + 7]);
            *(uint4*)(xl + (size_t)grow * HC + c0 + c) =
                make_uint4(*(unsigned*)&h0, *(unsigned*)&h1,
                           *(unsigned*)&h2, *(unsigned*)&h3);
        }
    } else {
        const int colC = dir * 128 + c0;
#pragma unroll
        for (int j = 0; j < 64; j += 4) {
            int gc = colC + j;
            float4 v = *(const float4*)(Crow + j);
            float4 sc = *(const float4*)(g_scale + gc);
            float4 sh = *(const float4*)(g_shift + gc);
            v.x = fmaxf(fmaf(v.x, sc.x, sh.x), 0.f);
            v.y = fmaxf(fmaf(v.y, sc.y, sh.y), 0.f);
            v.z = fmaxf(fmaf(v.z, sc.z, sh.z), 0.f);
            v.w = fmaxf(fmaf(v.w, sc.w, sh.w), 0.f);
            *(float4*)(Cout + (size_t)grow * 256 + gc) = v;
        }
    }
}

// ---------------- gather: warp per (node, direction), 4-wide edge unroll ----------------
__global__ void __launch_bounds__(256)
gather_kernel(const float* __restrict__ b_f, const float* __restrict__ b_b) {
    int wid = (blockIdx.x * blockDim.x + threadIdx.x) >> 5;
    int lane = threadIdx.x & 31;
    if (wid >= 2 * NN) return;
    bool back = wid >= NN;
    int n = back ? wid - NN : wid;
    int dir = back ? 1 : 0;
    const int* lst = g_adj[dir];
    const __half* xl = back ? g_xl_b : g_xl_f;
    const float* al = back ? g_al_b : g_al_f;
    const float* ar = back ? g_ar_b : g_ar_f;
    const float* bias = back ? b_b : b_f;

    int h = lane >> 3;
    float arh = __ldg(&ar[n * 4 + h]);
    int beg = g_off[dir][n];
    int end = (n == NN - 1) ? NEP : g_off[dir][n + 1];

    float4 acc = make_float4(0.f, 0.f, 0.f, 0.f);
    float den = 0.f;
    int j = beg;
    for (; j + 4 <= end; j += 4) {
        int s0 = __ldg(&lst[j + 0]);
        int s1 = __ldg(&lst[j + 1]);
        int s2 = __ldg(&lst[j + 2]);
        int s3 = __ldg(&lst[j + 3]);
        float a0 = __ldg(&al[s0 * 4 + h]);
        float a1 = __ldg(&al[s1 * 4 + h]);
        float a2 = __ldg(&al[s2 * 4 + h]);
        float a3 = __ldg(&al[s3 * 4 + h]);
        uint2 r0 = *(const uint2*)(xl + (size_t)s0 * HC + lane * 4);
        uint2 r1 = *(const uint2*)(xl + (size_t)s1 * HC + lane * 4);
        uint2 r2 = *(const uint2*)(xl + (size_t)s2 * HC + lane * 4);
        uint2 r3 = *(const uint2*)(xl + (size_t)s3 * HC + lane * 4);
        float w0 = __expf(lrelu(a0 + arh));
        float w1 = __expf(lrelu(a1 + arh));
        float w2 = __expf(lrelu(a2 + arh));
        float w3 = __expf(lrelu(a3 + arh));
        den += (w0 + w1) + (w2 + w3);
        float2 p, q;
        p = __half22float2(*(__half2*)&r0.x); q = __half22float2(*(__half2*)&r0.y);
        acc.x = fmaf(w0, p.x, acc.x); acc.y = fmaf(w0, p.y, acc.y);
        acc.z = fmaf(w0, q.x, acc.z); acc.w = fmaf(w0, q.y, acc.w);
        p = __half22float2(*(__half2*)&r1.x); q = __half22float2(*(__half2*)&r1.y);
        acc.x = fmaf(w1, p.x, acc.x); acc.y = fmaf(w1, p.y, acc.y);
        acc.z = fmaf(w1, q.x, acc.z); acc.w = fmaf(w1, q.y, acc.w);
        p = __half22float2(*(__half2*)&r2.x); q = __half22float2(*(__half2*)&r2.y);
        acc.x = fmaf(w2, p.x, acc.x); acc.y = fmaf(w2, p.y, acc.y);
        acc.z = fmaf(w2, q.x, acc.z); acc.w = fmaf(w2, q.y, acc.w);
        p = __half22float2(*(__half2*)&r3.x); q = __half22float2(*(__half2*)&r3.y);
        acc.x = fmaf(w3, p.x, acc.x); acc.y = fmaf(w3, p.y, acc.y);
        acc.z = fmaf(w3, q.x, acc.z); acc.w = fmaf(w3, q.y, acc.w);
    }
    for (; j < end; j++) {
        int s = __ldg(&lst[j]);
        float a = __ldg(&al[s * 4 + h]);
        uint2 raw = *(const uint2*)(xl + (size_t)s * HC + lane * 4);
        float w = __expf(lrelu(a + arh));
        float2 p = __half22float2(*(__half2*)&raw.x);
        float2 q = __half22float2(*(__half2*)&raw.y);
        acc.x = fmaf(w, p.x, acc.x); acc.y = fmaf(w, p.y, acc.y);
        acc.z = fmaf(w, q.x, acc.z); acc.w = fmaf(w, q.y, acc.w);
        den += w;
    }
    float inv = 1.f / (den + 1e-16f);
    float4 b4 = *(const float4*)(bias + lane * 4);
    float4 o;
    o.x = fmaf(acc.x, inv, b4.x);
    o.y = fmaf(acc.y, inv, b4.y);
    o.z = fmaf(acc.z, inv, b4.z);
    o.w = fmaf(acc.w, inv, b4.w);
    __half2 p0 = __floats2half2_rn(o.x, o.y);
    __half2 p1 = __floats2half2_rn(o.z, o.w);
    *(uint2*)(g_agg_h + (size_t)n * 256 + (back ? 128 : 0) + lane * 4) =
        make_uint2(*(unsigned*)&p0, *(unsigned*)&p1);
}

// ---------------- launch ----------------
extern "C" void kernel_launch(void* const* d_in, const int* in_sizes, int n_in,
                              void* d_out, int out_size) {
    const float* x        = (const float*)d_in[0];
    const int*   ei       = (const int*)d_in[1];
    const float* W_f      = (const float*)d_in[2];
    const float* a_src_f  = (const float*)d_in[3];
    const float* a_dst_f  = (const float*)d_in[4];
    const float* b_f      = (const float*)d_in[5];
    const float* W_b      = (const float*)d_in[6];
    const float* a_src_b  = (const float*)d_in[7];
    const float* a_dst_b  = (const float*)d_in[8];
    const float* b_b      = (const float*)d_in[9];
    const float* W_fuse   = (const float*)d_in[10];
    const float* b_fuse   = (const float*)d_in[11];
    const float* gamma    = (const float*)d_in[12];
    const float* beta     = (const float*)d_in[13];
    const float* run_mean = (const float*)d_in[14];
    const float* run_var  = (const float*)d_in[15];
    float* out = (float*)d_out;

    static cudaStream_t s1 = nullptr, s2 = nullptr;
    static cudaEvent_t ev_fork = nullptr, ev_j1 = nullptr, ev_j2 = nullptr;
    if (!s1) {
        cudaStreamCreateWithFlags(&s1, cudaStreamNonBlocking);
        cudaStreamCreateWithFlags(&s2, cudaStreamNonBlocking);
        cudaEventCreateWithFlags(&ev_fork, cudaEventDisableTiming);
        cudaEventCreateWithFlags(&ev_j1, cudaEventDisableTiming);
        cudaEventCreateWithFlags(&ev_j2, cudaEventDisableTiming);
        cudaFuncSetAttribute(hgemm_kernel<0>, cudaFuncAttributeMaxDynamicSharedMemorySize, SMEM_SZ);
        cudaFuncSetAttribute(hgemm_kernel<1>, cudaFuncAttributeMaxDynamicSharedMemorySize, SMEM_SZ);
    }

    cudaEventRecord(ev_fork, 0);
    cudaStreamWaitEvent(s1, ev_fork, 0);
    cudaStreamWaitEvent(s2, ev_fork, 0);

    // two parallel CSR chains (disjoint arrays)
    pack_kernel<<<(NN + 255) / 256, 256, 0, s1>>>(b_fuse, gamma, beta, run_mean, run_var, 0);
    hist_kernel<<<(NEP + 255) / 256, 256, 0, s1>>>(ei, 0);
    scan_kernel<<<1, 1024, 0, s1>>>(0);
    scatter_kernel<<<(NEP + 255) / 256, 256, 0, s1>>>(ei, 0);
    cudaEventRecord(ev_j1, s1);

    pack_kernel<<<(NN + 255) / 256, 256, 0, s2>>>(b_fuse, gamma, beta, run_mean, run_var, 1);
    hist_kernel<<<(NEP + 255) / 256, 256, 0, s2>>>(ei, 1);
    scan_kernel<<<1, 1024, 0, s2>>>(1);
    scatter_kernel<<<(NEP + 255) / 256, 256, 0, s2>>>(ei, 1);
    cudaEventRecord(ev_j2, s2);

    // main stream
    conv_w_kernel<<<(KDIM * 256 + 255) / 256, 256>>>(W_f, W_b, W_fuse);

    dim3 gg((NN + 127) / 128, 2);
    hgemm_kernel<0><<<gg, 256, SMEM_SZ>>>(x, nullptr, a_src_f, a_dst_f, a_src_b, a_dst_b);

    cudaStreamWaitEvent(0, ev_j1, 0);
    cudaStreamWaitEvent(0, ev_j2, 0);
    gather_kernel<<<(2 * NN * 32 + 255) / 256, 256>>>(b_f, b_b);

    hgemm_kernel<1><<<gg, 256, SMEM_SZ>>>(nullptr, out, nullptr, nullptr, nullptr, nullptr);
}

// round 6
// speedup vs baseline: 1.1537x; 1.1537x over previous
#include <cuda_runtime.h>
#include <cuda_fp16.h>
#include <mma.h>
using namespace nvcuda;

// ---------------- problem constants ----------------
#define NN   50000
#define NE   1600000
#define NEP  (NE + NN)      // edges + self loops
#define KDIM 256
#define HC   128
#define NEG  0.2f

// ---------------- device scratch ----------------
__device__ __half g_x_h[NN * KDIM];       // x in fp16
__device__ __half g_Bcat_h[KDIM * 256];   // [k][j]: j<128 -> W_f, else W_b
__device__ __half g_Wfuse_h[KDIM * 256];
__device__ __half g_xl_f[NN * HC];
__device__ __half g_xl_b[NN * HC];
__device__ __half g_agg_h[NN * 256];      // concat(agg_f, agg_b) fp16
__device__ float g_al_f[NN * 4];
__device__ float g_ar_f[NN * 4];
__device__ float g_al_b[NN * 4];
__device__ float g_ar_b[NN * 4];
__device__ float g_scale[256];
__device__ float g_shift[256];
// CSR scratch
__device__ int g_deg_in[NN];
__device__ int g_deg_out[NN];
__device__ int g_off_in[NN];
__device__ int g_off_out[NN];
__device__ int g_cur_in[NN];
__device__ int g_cur_out[NN];
__device__ int g_in_src[NEP];
__device__ int g_out_dst[NEP];

__device__ __forceinline__ float lrelu(float v) { return v > 0.f ? v : NEG * v; }

// ---------------- prep ----------------
__global__ void pack_kernel(const float* __restrict__ b_fuse,
                            const float* __restrict__ gamma, const float* __restrict__ beta,
                            const float* __restrict__ mean, const float* __restrict__ var) {
    int t = blockIdx.x * blockDim.x + threadIdx.x;
    if (t < NN) { g_deg_in[t] = 0; g_deg_out[t] = 0; }
    if (t < 256) {
        float inv = rsqrtf(var[t] + 1e-5f);
        float sc = gamma[t] * inv;
        g_scale[t] = sc;
        g_shift[t] = beta[t] + (b_fuse[t] - mean[t]) * sc;
    }
}

__global__ void conv_w_kernel(const float* __restrict__ Wf, const float* __restrict__ Wb,
                              const float* __restrict__ Wfu) {
    int t = blockIdx.x * blockDim.x + threadIdx.x;
    if (t < KDIM * 256) {
        int k = t >> 8, j = t & 255;
        float v = (j < HC) ? Wf[k * HC + j] : Wb[k * HC + (j - HC)];
        g_Bcat_h[t] = __float2half_rn(v);
        g_Wfuse_h[t] = __float2half_rn(Wfu[t]);
    }
}

__global__ void conv_x_kernel(const float* __restrict__ x) {
    int t = blockIdx.x * blockDim.x + threadIdx.x;
    if (t >= NN * KDIM / 8) return;
    float4 a = *(const float4*)(x + t * 8);
    float4 b = *(const float4*)(x + t * 8 + 4);
    __half2 h0 = __floats2half2_rn(a.x, a.y);
    __half2 h1 = __floats2half2_rn(a.z, a.w);
    __half2 h2 = __floats2half2_rn(b.x, b.y);
    __half2 h3 = __floats2half2_rn(b.z, b.w);
    *(uint4*)(g_x_h + t * 8) = make_uint4(*(unsigned*)&h0, *(unsigned*)&h1,
                                          *(unsigned*)&h2, *(unsigned*)&h3);
}

// ---------------- CSR build ----------------
__global__ void hist_kernel(const int* __restrict__ ei) {
    int idx = blockIdx.x * blockDim.x + threadIdx.x;
    if (idx >= NEP) return;
    int s, d;
    if (idx < NE) { s = __ldg(&ei[idx]); d = __ldg(&ei[NE + idx]); }
    else          { s = d = idx - NE; }
    atomicAdd(&g_deg_in[d], 1);
    atomicAdd(&g_deg_out[s], 1);
}

__global__ void scan_kernel() {
    __shared__ int part[1024];
    int* deg = blockIdx.x ? g_deg_out : g_deg_in;
    int* off = blockIdx.x ? g_off_out : g_off_in;
    int* cur = blockIdx.x ? g_cur_out : g_cur_in;
    int t = threadIdx.x;
    const int CH = (NN + 1023) / 1024;
    int base = t * CH;
    int s = 0;
    for (int i = 0; i < CH; i++) { int idx = base + i; if (idx < NN) s += deg[idx]; }
    part[t] = s;
    __syncthreads();
    for (int d = 1; d < 1024; d <<= 1) {
        int v = (t >= d) ? part[t - d] : 0;
        __syncthreads();
        part[t] += v;
        __syncthreads();
    }
    int pre = (t == 0) ? 0 : part[t - 1];
    for (int i = 0; i < CH; i++) {
        int idx = base + i;
        if (idx < NN) { off[idx] = pre; cur[idx] = pre; pre += deg[idx]; }
    }
}

__global__ void scatter_kernel(const int* __restrict__ ei) {
    int idx = blockIdx.x * blockDim.x + threadIdx.x;
    if (idx >= NEP) return;
    int s, d;
    if (idx < NE) { s = __ldg(&ei[idx]); d = __ldg(&ei[NE + idx]); }
    else          { s = d = idx - NE; }
    int p = atomicAdd(&g_cur_in[d], 1);
    g_in_src[p] = s;
    int q = atomicAdd(&g_cur_out[s], 1);
    g_out_dst[q] = d;
}

// ---------------- HMMA GEMM: 128x128 tile, BK=32, 8 warps (4M x 2N) ----------------
#define A_LDM 40
#define B_LDM 136
#define C_LDM 132
#define SMEM_SZ (128 * C_LDM * 4)

template <int MODE>
__global__ void __launch_bounds__(256)
hgemm_kernel(float* __restrict__ Cout,
             const float* __restrict__ asrc_f, const float* __restrict__ adst_f,
             const float* __restrict__ asrc_b, const float* __restrict__ adst_b) {
    extern __shared__ char sm_raw[];
    __half* As = (__half*)sm_raw;
    __half* Bs = (__half*)(sm_raw + 128 * A_LDM * 2);
    float* Cs = (float*)sm_raw;

    const int tid = threadIdx.x;
    const int warp = tid >> 5;
    const int wm = warp & 3;
    const int wn = warp >> 2;
    const int row0 = blockIdx.x * 128;
    const int dir = blockIdx.y;
    const int colB = dir * 128;

    const __half* Ag = (MODE == 0) ? g_x_h : g_agg_h;
    const __half* Bg = (MODE == 0) ? g_Bcat_h : g_Wfuse_h;

    wmma::fragment<wmma::accumulator, 16, 16, 16, float> acc[2][4];
#pragma unroll
    for (int i = 0; i < 2; i++)
#pragma unroll
        for (int j = 0; j < 4; j++) wmma::fill_fragment(acc[i][j], 0.f);

    for (int kt = 0; kt < KDIM; kt += 32) {
#pragma unroll
        for (int l = 0; l < 2; l++) {
            int c = tid + l * 256;
            int r = c >> 2;
            int c8 = (c & 3) * 8;
            int grow = row0 + r;
            uint4 v = make_uint4(0, 0, 0, 0);
            if (grow < NN) v = *(const uint4*)(Ag + (size_t)grow * KDIM + kt + c8);
            *(uint4*)(As + r * A_LDM + c8) = v;
        }
#pragma unroll
        for (int l = 0; l < 2; l++) {
            int c = tid + l * 256;
            int r = c >> 4;
            int c8 = (c & 15) * 8;
            *(uint4*)(Bs + r * B_LDM + c8) =
                *(const uint4*)(Bg + (size_t)(kt + r) * 256 + colB + c8);
        }
        __syncthreads();
#pragma unroll
        for (int kk = 0; kk < 32; kk += 16) {
            wmma::fragment<wmma::matrix_a, 16, 16, 16, __half, wmma::row_major> af[2];
            wmma::fragment<wmma::matrix_b, 16, 16, 16, __half, wmma::row_major> bf[4];
#pragma unroll
            for (int i = 0; i < 2; i++)
                wmma::load_matrix_sync(af[i], As + (wm * 32 + i * 16) * A_LDM + kk, A_LDM);
#pragma unroll
            for (int j = 0; j < 4; j++)
                wmma::load_matrix_sync(bf[j], Bs + kk * B_LDM + wn * 64 + j * 16, B_LDM);
#pragma unroll
            for (int i = 0; i < 2; i++)
#pragma unroll
                for (int j = 0; j < 4; j++)
                    wmma::mma_sync(acc[i][j], af[i], bf[j], acc[i][j]);
        }
        __syncthreads();
    }

#pragma unroll
    for (int i = 0; i < 2; i++)
#pragma unroll
        for (int j = 0; j < 4; j++)
            wmma::store_matrix_sync(Cs + (wm * 32 + i * 16) * C_LDM + wn * 64 + j * 16,
                                    acc[i][j], C_LDM, wmma::mem_row_major);
    __syncthreads();

    const int r = tid >> 1;
    const int c0 = (tid & 1) * 64;
    const int grow = row0 + r;
    if (grow >= NN) return;
    const float* Crow = Cs + r * C_LDM + c0;

    if (MODE == 0) {
        __half* xl = dir ? g_xl_b : g_xl_f;
        const float* asrc = dir ? asrc_b : asrc_f;
        const float* adst = dir ? adst_b : adst_f;
        float* alp = dir ? g_al_b : g_al_f;
        float* arp = dir ? g_ar_b : g_ar_f;
#pragma unroll
        for (int hh = 0; hh < 2; hh++) {
            int head = (tid & 1) * 2 + hh;
            float ps = 0.f, pd = 0.f;
#pragma unroll
            for (int c = 0; c < 32; c++) {
                float v = Crow[hh * 32 + c];
                ps = fmaf(v, __ldg(&asrc[head * 32 + c]), ps);
                pd = fmaf(v, __ldg(&adst[head * 32 + c]), pd);
            }
            alp[grow * 4 + head] = ps;
            arp[grow * 4 + head] = pd;
        }
#pragma unroll
        for (int c = 0; c < 64; c += 8) {
            __half2 h0 = __floats2half2_rn(Crow[c + 0], Crow[c + 1]);
            __half2 h1 = __floats2half2_rn(Crow[c + 2], Crow[c + 3]);
            __half2 h2 = __floats2half2_rn(Crow[c + 4], Crow[c + 5]);
            __half2 h3 = __floats2half2_rn(Crow[c + 6], Crow[c + 7]);
            *(uint4*)(xl + (size_t)grow * HC + c0 + c) =
                make_uint4(*(unsigned*)&h0, *(unsigned*)&h1,
                           *(unsigned*)&h2, *(unsigned*)&h3);
        }
    } else {
        const int colC = dir * 128 + c0;
#pragma unroll
        for (int j = 0; j < 64; j += 4) {
            int gc = colC + j;
            float4 v = *(const float4*)(Crow + j);
            float4 sc = *(const float4*)(g_scale + gc);
            float4 sh = *(const float4*)(g_shift + gc);
            v.x = fmaxf(fmaf(v.x, sc.x, sh.x), 0.f);
            v.y = fmaxf(fmaf(v.y, sc.y, sh.y), 0.f);
            v.z = fmaxf(fmaf(v.z, sc.z, sh.z), 0.f);
            v.w = fmaxf(fmaf(v.w, sc.w, sh.w), 0.f);
            *(float4*)(Cout + (size_t)grow * 256 + gc) = v;
        }
    }
}

// ---------------- gather: warp per (node, direction), 4-wide edge unroll ----------------
__global__ void __launch_bounds__(256)
gather_kernel(const float* __restrict__ b_f, const float* __restrict__ b_b) {
    int wid = (blockIdx.x * blockDim.x + threadIdx.x) >> 5;
    int lane = threadIdx.x & 31;
    if (wid >= 2 * NN) return;
    bool back = wid >= NN;
    int n = back ? wid - NN : wid;
    const int* off = back ? g_off_out : g_off_in;
    const int* lst = back ? g_out_dst : g_in_src;
    const __half* xl = back ? g_xl_b : g_xl_f;
    const float* al = back ? g_al_b : g_al_f;
    const float* ar = back ? g_ar_b : g_ar_f;
    const float* bias = back ? b_b : b_f;

    int h = lane >> 3;
    float arh = __ldg(&ar[n * 4 + h]);
    int beg = off[n];
    int end = (n == NN - 1) ? NEP : off[n + 1];

    float4 acc = make_float4(0.f, 0.f, 0.f, 0.f);
    float den = 0.f;
    int j = beg;
    for (; j + 4 <= end; j += 4) {
        int s0 = __ldg(&lst[j + 0]);
        int s1 = __ldg(&lst[j + 1]);
        int s2 = __ldg(&lst[j + 2]);
        int s3 = __ldg(&lst[j + 3]);
        float a0 = __ldg(&al[s0 * 4 + h]);
        float a1 = __ldg(&al[s1 * 4 + h]);
        float a2 = __ldg(&al[s2 * 4 + h]);
        float a3 = __ldg(&al[s3 * 4 + h]);
        uint2 r0 = *(const uint2*)(xl + (size_t)s0 * HC + lane * 4);
        uint2 r1 = *(const uint2*)(xl + (size_t)s1 * HC + lane * 4);
        uint2 r2 = *(const uint2*)(xl + (size_t)s2 * HC + lane * 4);
        uint2 r3 = *(const uint2*)(xl + (size_t)s3 * HC + lane * 4);
        float w0 = __expf(lrelu(a0 + arh));
        float w1 = __expf(lrelu(a1 + arh));
        float w2 = __expf(lrelu(a2 + arh));
        float w3 = __expf(lrelu(a3 + arh));
        den += (w0 + w1) + (w2 + w3);
        float2 p, q;
        p = __half22float2(*(__half2*)&r0.x); q = __half22float2(*(__half2*)&r0.y);
        acc.x = fmaf(w0, p.x, acc.x); acc.y = fmaf(w0, p.y, acc.y);
        acc.z = fmaf(w0, q.x, acc.z); acc.w = fmaf(w0, q.y, acc.w);
        p = __half22float2(*(__half2*)&r1.x); q = __half22float2(*(__half2*)&r1.y);
        acc.x = fmaf(w1, p.x, acc.x); acc.y = fmaf(w1, p.y, acc.y);
        acc.z = fmaf(w1, q.x, acc.z); acc.w = fmaf(w1, q.y, acc.w);
        p = __half22float2(*(__half2*)&r2.x); q = __half22float2(*(__half2*)&r2.y);
        acc.x = fmaf(w2, p.x, acc.x); acc.y = fmaf(w2, p.y, acc.y);
        acc.z = fmaf(w2, q.x, acc.z); acc.w = fmaf(w2, q.y, acc.w);
        p = __half22float2(*(__half2*)&r3.x); q = __half22float2(*(__half2*)&r3.y);
        acc.x = fmaf(w3, p.x, acc.x); acc.y = fmaf(w3, p.y, acc.y);
        acc.z = fmaf(w3, q.x, acc.z); acc.w = fmaf(w3, q.y, acc.w);
    }
    for (; j < end; j++) {
        int s = __ldg(&lst[j]);
        float a = __ldg(&al[s * 4 + h]);
        uint2 raw = *(const uint2*)(xl + (size_t)s * HC + lane * 4);
        float w = __expf(lrelu(a + arh));
        float2 p = __half22float2(*(__half2*)&raw.x);
        float2 q = __half22float2(*(__half2*)&raw.y);
        acc.x = fmaf(w, p.x, acc.x); acc.y = fmaf(w, p.y, acc.y);
        acc.z = fmaf(w, q.x, acc.z); acc.w = fmaf(w, q.y, acc.w);
        den += w;
    }
    float inv = 1.f / (den + 1e-16f);
    float4 b4 = *(const float4*)(bias + lane * 4);
    float4 o;
    o.x = fmaf(acc.x, inv, b4.x);
    o.y = fmaf(acc.y, inv, b4.y);
    o.z = fmaf(acc.z, inv, b4.z);
    o.w = fmaf(acc.w, inv, b4.w);
    __half2 p0 = __floats2half2_rn(o.x, o.y);
    __half2 p1 = __floats2half2_rn(o.z, o.w);
    *(uint2*)(g_agg_h + (size_t)n * 256 + (back ? 128 : 0) + lane * 4) =
        make_uint2(*(unsigned*)&p0, *(unsigned*)&p1);
}

// ---------------- launch ----------------
extern "C" void kernel_launch(void* const* d_in, const int* in_sizes, int n_in,
                              void* d_out, int out_size) {
    const float* x        = (const float*)d_in[0];
    const int*   ei       = (const int*)d_in[1];
    const float* W_f      = (const float*)d_in[2];
    const float* a_src_f  = (const float*)d_in[3];
    const float* a_dst_f  = (const float*)d_in[4];
    const float* b_f      = (const float*)d_in[5];
    const float* W_b      = (const float*)d_in[6];
    const float* a_src_b  = (const float*)d_in[7];
    const float* a_dst_b  = (const float*)d_in[8];
    const float* b_b      = (const float*)d_in[9];
    const float* W_fuse   = (const float*)d_in[10];
    const float* b_fuse   = (const float*)d_in[11];
    const float* gamma    = (const float*)d_in[12];
    const float* beta     = (const float*)d_in[13];
    const float* run_mean = (const float*)d_in[14];
    const float* run_var  = (const float*)d_in[15];
    float* out = (float*)d_out;

    static cudaStream_t s_side = nullptr;
    static cudaEvent_t ev_fork = nullptr, ev_join = nullptr;
    if (!s_side) {
        cudaStreamCreateWithFlags(&s_side, cudaStreamNonBlocking);
        cudaEventCreateWithFlags(&ev_fork, cudaEventDisableTiming);
        cudaEventCreateWithFlags(&ev_join, cudaEventDisableTiming);
        cudaFuncSetAttribute(hgemm_kernel<0>, cudaFuncAttributeMaxDynamicSharedMemorySize, SMEM_SZ);
        cudaFuncSetAttribute(hgemm_kernel<1>, cudaFuncAttributeMaxDynamicSharedMemorySize, SMEM_SZ);
    }

    cudaEventRecord(ev_fork, 0);
    cudaStreamWaitEvent(s_side, ev_fork, 0);

    // side stream: CSR build (depends only on edge_index)
    pack_kernel<<<(NN + 255) / 256, 256, 0, s_side>>>(b_fuse, gamma, beta, run_mean, run_var);
    hist_kernel<<<(NEP + 255) / 256, 256, 0, s_side>>>(ei);
    scan_kernel<<<2, 1024, 0, s_side>>>();
    scatter_kernel<<<(NEP + 255) / 256, 256, 0, s_side>>>(ei);
    cudaEventRecord(ev_join, s_side);

    // main stream
    conv_w_kernel<<<(KDIM * 256 + 255) / 256, 256>>>(W_f, W_b, W_fuse);
    conv_x_kernel<<<(NN * KDIM / 8 + 255) / 256, 256>>>(x);

    dim3 gg((NN + 127) / 128, 2);
    hgemm_kernel<0><<<gg, 256, SMEM_SZ>>>(nullptr, a_src_f, a_dst_f, a_src_b, a_dst_b);

    cudaStreamWaitEvent(0, ev_join, 0);
    gather_kernel<<<(2 * NN * 32 + 255) / 256, 256>>>(b_f, b_b);

    hgemm_kernel<1><<<gg, 256, SMEM_SZ>>>(out, nullptr, nullptr, nullptr, nullptr);
}

// round 7
// speedup vs baseline: 1.2486x; 1.0823x over previous
#include <cuda_runtime.h>
#include <cuda_fp16.h>
#include <mma.h>
using namespace nvcuda;

// ---------------- problem constants ----------------
#define NN   50000
#define NE   1600000
#define NEP  (NE + NN)      // edges + self loops
#define KDIM 256
#define HC   128
#define NEG  0.2f

// ---------------- device scratch ----------------
__device__ __half g_x_h[NN * KDIM];
__device__ __half g_Bcat_h[KDIM * 256];
__device__ __half g_Wfuse_h[KDIM * 256];
__device__ __half g_xl_f[NN * HC];
__device__ __half g_xl_b[NN * HC];
__device__ __half g_agg_h[NN * 256];
__device__ float g_al_f[NN * 4];
__device__ float g_ar_f[NN * 4];
__device__ float g_al_b[NN * 4];
__device__ float g_ar_b[NN * 4];
__device__ float g_scale[256];
__device__ float g_shift[256];
__device__ int g_deg_in[NN];
__device__ int g_deg_out[NN];
__device__ int g_off_in[NN];
__device__ int g_off_out[NN];
__device__ int g_cur_in[NN];
__device__ int g_cur_out[NN];
__device__ int g_in_src[NEP];
__device__ int g_out_dst[NEP];

__device__ __forceinline__ float lrelu(float v) { return v > 0.f ? v : NEG * v; }

// ---------------- prep ----------------
__global__ void pack_kernel(const float* __restrict__ b_fuse,
                            const float* __restrict__ gamma, const float* __restrict__ beta,
                            const float* __restrict__ mean, const float* __restrict__ var) {
    int t = blockIdx.x * blockDim.x + threadIdx.x;
    if (t < NN) { g_deg_in[t] = 0; g_deg_out[t] = 0; }
    if (t < 256) {
        float inv = rsqrtf(var[t] + 1e-5f);
        float sc = gamma[t] * inv;
        g_scale[t] = sc;
        g_shift[t] = beta[t] + (b_fuse[t] - mean[t]) * sc;
    }
}

__global__ void conv_w_kernel(const float* __restrict__ Wf, const float* __restrict__ Wb,
                              const float* __restrict__ Wfu) {
    int t = blockIdx.x * blockDim.x + threadIdx.x;
    if (t < KDIM * 256) {
        int k = t >> 8, j = t & 255;
        float v = (j < HC) ? Wf[k * HC + j] : Wb[k * HC + (j - HC)];
        g_Bcat_h[t] = __float2half_rn(v);
        g_Wfuse_h[t] = __float2half_rn(Wfu[t]);
    }
}

__global__ void conv_x_kernel(const float* __restrict__ x) {
    int t = blockIdx.x * blockDim.x + threadIdx.x;
    if (t >= NN * KDIM / 8) return;
    float4 a = *(const float4*)(x + t * 8);
    float4 b = *(const float4*)(x + t * 8 + 4);
    __half2 h0 = __floats2half2_rn(a.x, a.y);
    __half2 h1 = __floats2half2_rn(a.z, a.w);
    __half2 h2 = __floats2half2_rn(b.x, b.y);
    __half2 h3 = __floats2half2_rn(b.z, b.w);
    *(uint4*)(g_x_h + t * 8) = make_uint4(*(unsigned*)&h0, *(unsigned*)&h1,
                                          *(unsigned*)&h2, *(unsigned*)&h3);
}

// ---------------- CSR build (4 edges per thread; NE % 4 == 0) ----------------
__global__ void hist_kernel(const int* __restrict__ ei) {
    int base = (blockIdx.x * blockDim.x + threadIdx.x) * 4;
    if (base >= NEP) return;
    if (base + 4 <= NE) {
        int4 s4 = *(const int4*)(ei + base);
        int4 d4 = *(const int4*)(ei + NE + base);
        atomicAdd(&g_deg_in[d4.x], 1);
        atomicAdd(&g_deg_in[d4.y], 1);
        atomicAdd(&g_deg_in[d4.z], 1);
        atomicAdd(&g_deg_in[d4.w], 1);
        atomicAdd(&g_deg_out[s4.x], 1);
        atomicAdd(&g_deg_out[s4.y], 1);
        atomicAdd(&g_deg_out[s4.z], 1);
        atomicAdd(&g_deg_out[s4.w], 1);
    } else {
#pragma unroll
        for (int i = 0; i < 4; i++) {
            int idx = base + i;
            if (idx >= NEP) break;
            int n = idx - NE;      // base >= NE here (NE % 4 == 0)
            atomicAdd(&g_deg_in[n], 1);
            atomicAdd(&g_deg_out[n], 1);
        }
    }
}

__global__ void scan_kernel() {
    __shared__ int part[1024];
    int* deg = blockIdx.x ? g_deg_out : g_deg_in;
    int* off = blockIdx.x ? g_off_out : g_off_in;
    int* cur = blockIdx.x ? g_cur_out : g_cur_in;
    int t = threadIdx.x;
    const int CH = (NN + 1023) / 1024;
    int base = t * CH;
    int s = 0;
    for (int i = 0; i < CH; i++) { int idx = base + i; if (idx < NN) s += deg[idx]; }
    part[t] = s;
    __syncthreads();
    for (int d = 1; d < 1024; d <<= 1) {
        int v = (t >= d) ? part[t - d] : 0;
        __syncthreads();
        part[t] += v;
        __syncthreads();
    }
    int pre = (t == 0) ? 0 : part[t - 1];
    for (int i = 0; i < CH; i++) {
        int idx = base + i;
        if (idx < NN) { off[idx] = pre; cur[idx] = pre; pre += deg[idx]; }
    }
}

__global__ void scatter_kernel(const int* __restrict__ ei) {
    int base = (blockIdx.x * blockDim.x + threadIdx.x) * 4;
    if (base >= NEP) return;
    if (base + 4 <= NE) {
        int4 s4 = *(const int4*)(ei + base);
        int4 d4 = *(const int4*)(ei + NE + base);
        int p0 = atomicAdd(&g_cur_in[d4.x], 1);
        int p1 = atomicAdd(&g_cur_in[d4.y], 1);
        int p2 = atomicAdd(&g_cur_in[d4.z], 1);
        int p3 = atomicAdd(&g_cur_in[d4.w], 1);
        int q0 = atomicAdd(&g_cur_out[s4.x], 1);
        int q1 = atomicAdd(&g_cur_out[s4.y], 1);
        int q2 = atomicAdd(&g_cur_out[s4.z], 1);
        int q3 = atomicAdd(&g_cur_out[s4.w], 1);
        g_in_src[p0] = s4.x;
        g_in_src[p1] = s4.y;
        g_in_src[p2] = s4.z;
        g_in_src[p3] = s4.w;
        g_out_dst[q0] = d4.x;
        g_out_dst[q1] = d4.y;
        g_out_dst[q2] = d4.z;
        g_out_dst[q3] = d4.w;
    } else {
#pragma unroll
        for (int i = 0; i < 4; i++) {
            int idx = base + i;
            if (idx >= NEP) break;
            int n = idx - NE;
            int p = atomicAdd(&g_cur_in[n], 1);
            g_in_src[p] = n;
            int q = atomicAdd(&g_cur_out[n], 1);
            g_out_dst[q] = n;
        }
    }
}

// ---------------- HMMA GEMM: 128x128 tile, BK=32, 8 warps (unchanged from R6) ----------------
#define A_LDM 40
#define B_LDM 136
#define C_LDM 132
#define SMEM_SZ (128 * C_LDM * 4)

template <int MODE>
__global__ void __launch_bounds__(256)
hgemm_kernel(float* __restrict__ Cout,
             const float* __restrict__ asrc_f, const float* __restrict__ adst_f,
             const float* __restrict__ asrc_b, const float* __restrict__ adst_b) {
    extern __shared__ char sm_raw[];
    __half* As = (__half*)sm_raw;
    __half* Bs = (__half*)(sm_raw + 128 * A_LDM * 2);
    float* Cs = (float*)sm_raw;

    const int tid = threadIdx.x;
    const int warp = tid >> 5;
    const int wm = warp & 3;
    const int wn = warp >> 2;
    const int row0 = blockIdx.x * 128;
    const int dir = blockIdx.y;
    const int colB = dir * 128;

    const __half* Ag = (MODE == 0) ? g_x_h : g_agg_h;
    const __half* Bg = (MODE == 0) ? g_Bcat_h : g_Wfuse_h;

    wmma::fragment<wmma::accumulator, 16, 16, 16, float> acc[2][4];
#pragma unroll
    for (int i = 0; i < 2; i++)
#pragma unroll
        for (int j = 0; j < 4; j++) wmma::fill_fragment(acc[i][j], 0.f);

    for (int kt = 0; kt < KDIM; kt += 32) {
#pragma unroll
        for (int l = 0; l < 2; l++) {
            int c = tid + l * 256;
            int r = c >> 2;
            int c8 = (c & 3) * 8;
            int grow = row0 + r;
            uint4 v = make_uint4(0, 0, 0, 0);
            if (grow < NN) v = *(const uint4*)(Ag + (size_t)grow * KDIM + kt + c8);
            *(uint4*)(As + r * A_LDM + c8) = v;
        }
#pragma unroll
        for (int l = 0; l < 2; l++) {
            int c = tid + l * 256;
            int r = c >> 4;
            int c8 = (c & 15) * 8;
            *(uint4*)(Bs + r * B_LDM + c8) =
                *(const uint4*)(Bg + (size_t)(kt + r) * 256 + colB + c8);
        }
        __syncthreads();
#pragma unroll
        for (int kk = 0; kk < 32; kk += 16) {
            wmma::fragment<wmma::matrix_a, 16, 16, 16, __half, wmma::row_major> af[2];
            wmma::fragment<wmma::matrix_b, 16, 16, 16, __half, wmma::row_major> bf[4];
#pragma unroll
            for (int i = 0; i < 2; i++)
                wmma::load_matrix_sync(af[i], As + (wm * 32 + i * 16) * A_LDM + kk, A_LDM);
#pragma unroll
            for (int j = 0; j < 4; j++)
                wmma::load_matrix_sync(bf[j], Bs + kk * B_LDM + wn * 64 + j * 16, B_LDM);
#pragma unroll
            for (int i = 0; i < 2; i++)
#pragma unroll
                for (int j = 0; j < 4; j++)
                    wmma::mma_sync(acc[i][j], af[i], bf[j], acc[i][j]);
        }
        __syncthreads();
    }

#pragma unroll
    for (int i = 0; i < 2; i++)
#pragma unroll
        for (int j = 0; j < 4; j++)
            wmma::store_matrix_sync(Cs + (wm * 32 + i * 16) * C_LDM + wn * 64 + j * 16,
                                    acc[i][j], C_LDM, wmma::mem_row_major);
    __syncthreads();

    const int r = tid >> 1;
    const int c0 = (tid & 1) * 64;
    const int grow = row0 + r;
    if (grow >= NN) return;
    const float* Crow = Cs + r * C_LDM + c0;

    if (MODE == 0) {
        __half* xl = dir ? g_xl_b : g_xl_f;
        const float* asrc = dir ? asrc_b : asrc_f;
        const float* adst = dir ? adst_b : adst_f;
        float* alp = dir ? g_al_b : g_al_f;
        float* arp = dir ? g_ar_b : g_ar_f;
#pragma unroll
        for (int hh = 0; hh < 2; hh++) {
            int head = (tid & 1) * 2 + hh;
            float ps = 0.f, pd = 0.f;
#pragma unroll
            for (int c = 0; c < 32; c++) {
                float v = Crow[hh * 32 + c];
                ps = fmaf(v, __ldg(&asrc[head * 32 + c]), ps);
                pd = fmaf(v, __ldg(&adst[head * 32 + c]), pd);
            }
            alp[grow * 4 + head] = ps;
            arp[grow * 4 + head] = pd;
        }
#pragma unroll
        for (int c = 0; c < 64; c += 8) {
            __half2 h0 = __floats2half2_rn(Crow[c + 0], Crow[c + 1]);
            __half2 h1 = __floats2half2_rn(Crow[c + 2], Crow[c + 3]);
            __half2 h2 = __floats2half2_rn(Crow[c + 4], Crow[c + 5]);
            __half2 h3 = __floats2half2_rn(Crow[c + 6], Crow[c + 7]);
            *(uint4*)(xl + (size_t)grow * HC + c0 + c) =
                make_uint4(*(unsigned*)&h0, *(unsigned*)&h1,
                           *(unsigned*)&h2, *(unsigned*)&h3);
        }
    } else {
        const int colC = dir * 128 + c0;
#pragma unroll
        for (int j = 0; j < 64; j += 4) {
            int gc = colC + j;
            float4 v = *(const float4*)(Crow + j);
            float4 sc = *(const float4*)(g_scale + gc);
            float4 sh = *(const float4*)(g_shift + gc);
            v.x = fmaxf(fmaf(v.x, sc.x, sh.x), 0.f);
            v.y = fmaxf(fmaf(v.y, sc.y, sh.y), 0.f);
            v.z = fmaxf(fmaf(v.z, sc.z, sh.z), 0.f);
            v.w = fmaxf(fmaf(v.w, sc.w, sh.w), 0.f);
            *(float4*)(Cout + (size_t)grow * 256 + gc) = v;
        }
    }
}

// ---------------- gather v2: 2 edges per warp (16 lanes x 8 halves each) ----------------
__global__ void __launch_bounds__(256)
gather_kernel(const float* __restrict__ b_f, const float* __restrict__ b_b) {
    int wid = (blockIdx.x * blockDim.x + threadIdx.x) >> 5;
    int lane = threadIdx.x & 31;
    if (wid >= 2 * NN) return;
    bool back = wid >= NN;
    int n = back ? wid - NN : wid;
    const int* off = back ? g_off_out : g_off_in;
    const int* lst = back ? g_out_dst : g_in_src;
    const __half* xl = back ? g_xl_b : g_xl_f;
    const float* al = back ? g_al_b : g_al_f;
    const float* ar = back ? g_ar_b : g_ar_f;
    const float* bias = back ? b_b : b_f;

    const int half = lane >> 4;   // which of 2 concurrent edges
    const int sub = lane & 15;    // 16 lanes per edge, 8 halves each
    const int h = sub >> 2;       // head (4 lanes of 8 ch = 32 ch per head)
    float arh = __ldg(&ar[n * 4 + h]);
    int beg = off[n];
    int end = (n == NN - 1) ? NEP : off[n + 1];

    float acc[8] = {0.f, 0.f, 0.f, 0.f, 0.f, 0.f, 0.f, 0.f};
    float den = 0.f;
    int j = beg + half;
    // unroll 2 per half: edges j and j+2 (stride 4 over the list)
    for (; j + 2 < end; j += 4) {
        int s0 = __ldg(&lst[j]);
        int s1 = __ldg(&lst[j + 2]);
        float a0 = __ldg(&al[s0 * 4 + h]);
        float a1 = __ldg(&al[s1 * 4 + h]);
        uint4 r0 = *(const uint4*)(xl + (size_t)s0 * HC + sub * 8);
        uint4 r1 = *(const uint4*)(xl + (size_t)s1 * HC + sub * 8);
        float w0 = __expf(lrelu(a0 + arh));
        float w1 = __expf(lrelu(a1 + arh));
        den += w0 + w1;
        float2 p;
        p = __half22float2(*(__half2*)&r0.x); acc[0] = fmaf(w0, p.x, acc[0]); acc[1] = fmaf(w0, p.y, acc[1]);
        p = __half22float2(*(__half2*)&r0.y); acc[2] = fmaf(w0, p.x, acc[2]); acc[3] = fmaf(w0, p.y, acc[3]);
        p = __half22float2(*(__half2*)&r0.z); acc[4] = fmaf(w0, p.x, acc[4]); acc[5] = fmaf(w0, p.y, acc[5]);
        p = __half22float2(*(__half2*)&r0.w); acc[6] = fmaf(w0, p.x, acc[6]); acc[7] = fmaf(w0, p.y, acc[7]);
        p = __half22float2(*(__half2*)&r1.x); acc[0] = fmaf(w1, p.x, acc[0]); acc[1] = fmaf(w1, p.y, acc[1]);
        p = __half22float2(*(__half2*)&r1.y); acc[2] = fmaf(w1, p.x, acc[2]); acc[3] = fmaf(w1, p.y, acc[3]);
        p = __half22float2(*(__half2*)&r1.z); acc[4] = fmaf(w1, p.x, acc[4]); acc[5] = fmaf(w1, p.y, acc[5]);
        p = __half22float2(*(__half2*)&r1.w); acc[6] = fmaf(w1, p.x, acc[6]); acc[7] = fmaf(w1, p.y, acc[7]);
    }
    for (; j < end; j += 2) {
        int s = __ldg(&lst[j]);
        float a = __ldg(&al[s * 4 + h]);
        uint4 r0 = *(const uint4*)(xl + (size_t)s * HC + sub * 8);
        float w = __expf(lrelu(a + arh));
        den += w;
        float2 p;
        p = __half22float2(*(__half2*)&r0.x); acc[0] = fmaf(w, p.x, acc[0]); acc[1] = fmaf(w, p.y, acc[1]);
        p = __half22float2(*(__half2*)&r0.y); acc[2] = fmaf(w, p.x, acc[2]); acc[3] = fmaf(w, p.y, acc[3]);
        p = __half22float2(*(__half2*)&r0.z); acc[4] = fmaf(w, p.x, acc[4]); acc[5] = fmaf(w, p.y, acc[5]);
        p = __half22float2(*(__half2*)&r0.w); acc[6] = fmaf(w, p.x, acc[6]); acc[7] = fmaf(w, p.y, acc[7]);
    }
    // combine the two halves
    den += __shfl_xor_sync(0xffffffffu, den, 16);
#pragma unroll
    for (int c = 0; c < 8; c++) acc[c] += __shfl_xor_sync(0xffffffffu, acc[c], 16);

    if (half == 0) {
        float inv = 1.f / (den + 1e-16f);
        float4 b0 = *(const float4*)(bias + sub * 8);
        float4 b1 = *(const float4*)(bias + sub * 8 + 4);
        float o0 = fmaf(acc[0], inv, b0.x), o1 = fmaf(acc[1], inv, b0.y);
        float o2 = fmaf(acc[2], inv, b0.z), o3 = fmaf(acc[3], inv, b0.w);
        float o4 = fmaf(acc[4], inv, b1.x), o5 = fmaf(acc[5], inv, b1.y);
        float o6 = fmaf(acc[6], inv, b1.z), o7 = fmaf(acc[7], inv, b1.w);
        __half2 h0 = __floats2half2_rn(o0, o1);
        __half2 h1 = __floats2half2_rn(o2, o3);
        __half2 h2 = __floats2half2_rn(o4, o5);
        __half2 h3 = __floats2half2_rn(o6, o7);
        *(uint4*)(g_agg_h + (size_t)n * 256 + (back ? 128 : 0) + sub * 8) =
            make_uint4(*(unsigned*)&h0, *(unsigned*)&h1,
                       *(unsigned*)&h2, *(unsigned*)&h3);
    }
}

// ---------------- launch ----------------
extern "C" void kernel_launch(void* const* d_in, const int* in_sizes, int n_in,
                              void* d_out, int out_size) {
    const float* x        = (const float*)d_in[0];
    const int*   ei       = (const int*)d_in[1];
    const float* W_f      = (const float*)d_in[2];
    const float* a_src_f  = (const float*)d_in[3];
    const float* a_dst_f  = (const float*)d_in[4];
    const float* b_f      = (const float*)d_in[5];
    const float* W_b      = (const float*)d_in[6];
    const float* a_src_b  = (const float*)d_in[7];
    const float* a_dst_b  = (const float*)d_in[8];
    const float* b_b      = (const float*)d_in[9];
    const float* W_fuse   = (const float*)d_in[10];
    const float* b_fuse   = (const float*)d_in[11];
    const float* gamma    = (const float*)d_in[12];
    const float* beta     = (const float*)d_in[13];
    const float* run_mean = (const float*)d_in[14];
    const float* run_var  = (const float*)d_in[15];
    float* out = (float*)d_out;

    static cudaStream_t s_side = nullptr;
    static cudaEvent_t ev_fork = nullptr, ev_join = nullptr;
    if (!s_side) {
        cudaStreamCreateWithFlags(&s_side, cudaStreamNonBlocking);
        cudaEventCreateWithFlags(&ev_fork, cudaEventDisableTiming);
        cudaEventCreateWithFlags(&ev_join, cudaEventDisableTiming);
        cudaFuncSetAttribute(hgemm_kernel<0>, cudaFuncAttributeMaxDynamicSharedMemorySize, SMEM_SZ);
        cudaFuncSetAttribute(hgemm_kernel<1>, cudaFuncAttributeMaxDynamicSharedMemorySize, SMEM_SZ);
    }

    cudaEventRecord(ev_fork, 0);
    cudaStreamWaitEvent(s_side, ev_fork, 0);

    // side stream: CSR build (depends only on edge_index)
    pack_kernel<<<(NN + 255) / 256, 256, 0, s_side>>>(b_fuse, gamma, beta, run_mean, run_var);
    hist_kernel<<<(NEP / 4 + 255) / 256, 256, 0, s_side>>>(ei);
    scan_kernel<<<2, 1024, 0, s_side>>>();
    scatter_kernel<<<(NEP / 4 + 255) / 256, 256, 0, s_side>>>(ei);
    cudaEventRecord(ev_join, s_side);

    // main stream
    conv_w_kernel<<<(KDIM * 256 + 255) / 256, 256>>>(W_f, W_b, W_fuse);
    conv_x_kernel<<<(NN * KDIM / 8 + 255) / 256, 256>>>(x);

    dim3 gg((NN + 127) / 128, 2);
    hgemm_kernel<0><<<gg, 256, SMEM_SZ>>>(nullptr, a_src_f, a_dst_f, a_src_b, a_dst_b);

    cudaStreamWaitEvent(0, ev_join, 0);
    gather_kernel<<<(2 * NN * 32 + 255) / 256, 256>>>(b_f, b_b);

    hgemm_kernel<1><<<gg, 256, SMEM_SZ>>>(out, nullptr, nullptr, nullptr, nullptr);
}

// round 8
// speedup vs baseline: 1.2858x; 1.0298x over previous
#include <cuda_runtime.h>
#include <cuda_fp16.h>
#include <mma.h>
using namespace nvcuda;

// ---------------- problem constants ----------------
#define NN   50000
#define NE   1600000
#define NEP  (NE + NN)      // edges + self loops
#define KDIM 256
#define HC   128
#define NEG  0.2f

// ---------------- device scratch ----------------
__device__ __half g_x_h[NN * KDIM];
__device__ __half g_Bcat_h[KDIM * 256];
__device__ __half g_Wfuse_h[KDIM * 256];
__device__ __half g_xl_f[NN * HC];
__device__ __half g_xl_b[NN * HC];
__device__ __half g_agg_h[NN * 256];
__device__ float g_al_f[NN * 4];
__device__ float g_ar_f[NN * 4];
__device__ float g_al_b[NN * 4];
__device__ float g_ar_b[NN * 4];
__device__ float g_scale[256];
__device__ float g_shift[256];
__device__ int g_deg_in[NN];
__device__ int g_deg_out[NN];
__device__ int g_off_in[NN];
__device__ int g_off_out[NN];
__device__ int g_cur_in[NN];
__device__ int g_cur_out[NN];
__device__ int g_in_src[NEP];
__device__ int g_out_dst[NEP];

__device__ __forceinline__ float lrelu(float v) { return v > 0.f ? v : NEG * v; }

// ---------------- prep ----------------
__global__ void pack_kernel(const float* __restrict__ b_fuse,
                            const float* __restrict__ gamma, const float* __restrict__ beta,
                            const float* __restrict__ mean, const float* __restrict__ var) {
    int t = blockIdx.x * blockDim.x + threadIdx.x;
    if (t < NN) { g_deg_in[t] = 0; g_deg_out[t] = 0; }
    if (t < 256) {
        float inv = rsqrtf(var[t] + 1e-5f);
        float sc = gamma[t] * inv;
        g_scale[t] = sc;
        g_shift[t] = beta[t] + (b_fuse[t] - mean[t]) * sc;
    }
}

__global__ void conv_w_kernel(const float* __restrict__ Wf, const float* __restrict__ Wb,
                              const float* __restrict__ Wfu) {
    int t = blockIdx.x * blockDim.x + threadIdx.x;
    if (t < KDIM * 256) {
        int k = t >> 8, j = t & 255;
        float v = (j < HC) ? Wf[k * HC + j] : Wb[k * HC + (j - HC)];
        g_Bcat_h[t] = __float2half_rn(v);
        g_Wfuse_h[t] = __float2half_rn(Wfu[t]);
    }
}

__global__ void conv_x_kernel(const float* __restrict__ x) {
    int t = blockIdx.x * blockDim.x + threadIdx.x;
    if (t >= NN * KDIM / 8) return;
    float4 a = *(const float4*)(x + t * 8);
    float4 b = *(const float4*)(x + t * 8 + 4);
    __half2 h0 = __floats2half2_rn(a.x, a.y);
    __half2 h1 = __floats2half2_rn(a.z, a.w);
    __half2 h2 = __floats2half2_rn(b.x, b.y);
    __half2 h3 = __floats2half2_rn(b.z, b.w);
    *(uint4*)(g_x_h + t * 8) = make_uint4(*(unsigned*)&h0, *(unsigned*)&h1,
                                          *(unsigned*)&h2, *(unsigned*)&h3);
}

// ---------------- CSR build ----------------
__global__ void hist_kernel(const int* __restrict__ ei) {
    int base = (blockIdx.x * blockDim.x + threadIdx.x) * 4;
    if (base >= NEP) return;
    if (base + 4 <= NE) {
        int4 s4 = *(const int4*)(ei + base);
        int4 d4 = *(const int4*)(ei + NE + base);
        atomicAdd(&g_deg_in[d4.x], 1);
        atomicAdd(&g_deg_in[d4.y], 1);
        atomicAdd(&g_deg_in[d4.z], 1);
        atomicAdd(&g_deg_in[d4.w], 1);
        atomicAdd(&g_deg_out[s4.x], 1);
        atomicAdd(&g_deg_out[s4.y], 1);
        atomicAdd(&g_deg_out[s4.z], 1);
        atomicAdd(&g_deg_out[s4.w], 1);
    } else {
#pragma unroll
        for (int i = 0; i < 4; i++) {
            int idx = base + i;
            if (idx >= NEP) break;
            int n = idx - NE;      // base >= NE here (NE % 4 == 0)
            atomicAdd(&g_deg_in[n], 1);
            atomicAdd(&g_deg_out[n], 1);
        }
    }
}

__global__ void scan_kernel() {
    __shared__ int part[1024];
    int* deg = blockIdx.x ? g_deg_out : g_deg_in;
    int* off = blockIdx.x ? g_off_out : g_off_in;
    int* cur = blockIdx.x ? g_cur_out : g_cur_in;
    int t = threadIdx.x;
    const int CH = (NN + 1023) / 1024;
    int base = t * CH;
    int s = 0;
    for (int i = 0; i < CH; i++) { int idx = base + i; if (idx < NN) s += deg[idx]; }
    part[t] = s;
    __syncthreads();
    for (int d = 1; d < 1024; d <<= 1) {
        int v = (t >= d) ? part[t - d] : 0;
        __syncthreads();
        part[t] += v;
        __syncthreads();
    }
    int pre = (t == 0) ? 0 : part[t - 1];
    for (int i = 0; i < CH; i++) {
        int idx = base + i;
        if (idx < NN) { off[idx] = pre; cur[idx] = pre; pre += deg[idx]; }
    }
}

__global__ void scatter_kernel(const int* __restrict__ ei) {
    int idx = blockIdx.x * blockDim.x + threadIdx.x;
    if (idx >= NEP) return;
    int s, d;
    if (idx < NE) { s = __ldg(&ei[idx]); d = __ldg(&ei[NE + idx]); }
    else          { s = d = idx - NE; }
    int p = atomicAdd(&g_cur_in[d], 1);
    g_in_src[p] = s;
    int q = atomicAdd(&g_cur_out[s], 1);
    g_out_dst[q] = d;
}

// ---------------- HMMA GEMM: 128x128 tile, BK=32, 8 warps ----------------
#define A_LDM 40
#define B_LDM 136
#define C_LDM 132
#define SMEM_SZ (128 * C_LDM * 4)

template <int MODE>
__global__ void __launch_bounds__(256)
hgemm_kernel(float* __restrict__ Cout,
             const float* __restrict__ asrc_f, const float* __restrict__ adst_f,
             const float* __restrict__ asrc_b, const float* __restrict__ adst_b) {
    extern __shared__ char sm_raw[];
    __half* As = (__half*)sm_raw;
    __half* Bs = (__half*)(sm_raw + 128 * A_LDM * 2);
    float* Cs = (float*)sm_raw;

    const int tid = threadIdx.x;
    const int warp = tid >> 5;
    const int wm = warp & 3;
    const int wn = warp >> 2;
    const int row0 = blockIdx.x * 128;
    const int dir = blockIdx.y;
    const int colB = dir * 128;

    const __half* Ag = (MODE == 0) ? g_x_h : g_agg_h;
    const __half* Bg = (MODE == 0) ? g_Bcat_h : g_Wfuse_h;

    wmma::fragment<wmma::accumulator, 16, 16, 16, float> acc[2][4];
#pragma unroll
    for (int i = 0; i < 2; i++)
#pragma unroll
        for (int j = 0; j < 4; j++) wmma::fill_fragment(acc[i][j], 0.f);

    for (int kt = 0; kt < KDIM; kt += 32) {
#pragma unroll
        for (int l = 0; l < 2; l++) {
            int c = tid + l * 256;
            int r = c >> 2;
            int c8 = (c & 3) * 8;
            int grow = row0 + r;
            uint4 v = make_uint4(0, 0, 0, 0);
            if (grow < NN) v = *(const uint4*)(Ag + (size_t)grow * KDIM + kt + c8);
            *(uint4*)(As + r * A_LDM + c8) = v;
        }
#pragma unroll
        for (int l = 0; l < 2; l++) {
            int c = tid + l * 256;
            int r = c >> 4;
            int c8 = (c & 15) * 8;
            *(uint4*)(Bs + r * B_LDM + c8) =
                *(const uint4*)(Bg + (size_t)(kt + r) * 256 + colB + c8);
        }
        __syncthreads();
#pragma unroll
        for (int kk = 0; kk < 32; kk += 16) {
            wmma::fragment<wmma::matrix_a, 16, 16, 16, __half, wmma::row_major> af[2];
            wmma::fragment<wmma::matrix_b, 16, 16, 16, __half, wmma::row_major> bf[4];
#pragma unroll
            for (int i = 0; i < 2; i++)
                wmma::load_matrix_sync(af[i], As + (wm * 32 + i * 16) * A_LDM + kk, A_LDM);
#pragma unroll
            for (int j = 0; j < 4; j++)
                wmma::load_matrix_sync(bf[j], Bs + kk * B_LDM + wn * 64 + j * 16, B_LDM);
#pragma unroll
            for (int i = 0; i < 2; i++)
#pragma unroll
                for (int j = 0; j < 4; j++)
                    wmma::mma_sync(acc[i][j], af[i], bf[j], acc[i][j]);
        }
        __syncthreads();
    }

#pragma unroll
    for (int i = 0; i < 2; i++)
#pragma unroll
        for (int j = 0; j < 4; j++)
            wmma::store_matrix_sync(Cs + (wm * 32 + i * 16) * C_LDM + wn * 64 + j * 16,
                                    acc[i][j], C_LDM, wmma::mem_row_major);
    __syncthreads();

    const int r = tid >> 1;
    const int c0 = (tid & 1) * 64;
    const int grow = row0 + r;
    if (grow >= NN) return;
    const float* Crow = Cs + r * C_LDM + c0;

    if (MODE == 0) {
        __half* xl = dir ? g_xl_b : g_xl_f;
        const float* asrc = dir ? asrc_b : asrc_f;
        const float* adst = dir ? adst_b : adst_f;
        float* alp = dir ? g_al_b : g_al_f;
        float* arp = dir ? g_ar_b : g_ar_f;
#pragma unroll
        for (int hh = 0; hh < 2; hh++) {
            int head = (tid & 1) * 2 + hh;
            float ps = 0.f, pd = 0.f;
#pragma unroll
            for (int c = 0; c < 32; c++) {
                float v = Crow[hh * 32 + c];
                ps = fmaf(v, __ldg(&asrc[head * 32 + c]), ps);
                pd = fmaf(v, __ldg(&adst[head * 32 + c]), pd);
            }
            alp[grow * 4 + head] = ps;
            arp[grow * 4 + head] = pd;
        }
#pragma unroll
        for (int c = 0; c < 64; c += 8) {
            __half2 h0 = __floats2half2_rn(Crow[c + 0], Crow[c + 1]);
            __half2 h1 = __floats2half2_rn(Crow[c + 2], Crow[c + 3]);
            __half2 h2 = __floats2half2_rn(Crow[c + 4], Crow[c + 5]);
            __half2 h3 = __floats2half2_rn(Crow[c + 6], Crow[c + 7]);
            *(uint4*)(xl + (size_t)grow * HC + c0 + c) =
                make_uint4(*(unsigned*)&h0, *(unsigned*)&h1,
                           *(unsigned*)&h2, *(unsigned*)&h3);
        }
    } else {
        const int colC = dir * 128 + c0;
#pragma unroll
        for (int j = 0; j < 64; j += 4) {
            int gc = colC + j;
            float4 v = *(const float4*)(Crow + j);
            float4 sc = *(const float4*)(g_scale + gc);
            float4 sh = *(const float4*)(g_shift + gc);
            v.x = fmaxf(fmaf(v.x, sc.x, sh.x), 0.f);
            v.y = fmaxf(fmaf(v.y, sc.y, sh.y), 0.f);
            v.z = fmaxf(fmaf(v.z, sc.z, sh.z), 0.f);
            v.w = fmaxf(fmaf(v.w, sc.w, sh.w), 0.f);
            *(float4*)(Cout + (size_t)grow * 256 + gc) = v;
        }
    }
}

// ---------------- gather v3: 2 edges per warp, 4 edges in flight per half ----------------
__global__ void __launch_bounds__(256)
gather_kernel(const float* __restrict__ b_f, const float* __restrict__ b_b) {
    int wid = (blockIdx.x * blockDim.x + threadIdx.x) >> 5;
    int lane = threadIdx.x & 31;
    if (wid >= 2 * NN) return;
    bool back = wid >= NN;
    int n = back ? wid - NN : wid;
    const int* off = back ? g_off_out : g_off_in;
    const int* lst = back ? g_out_dst : g_in_src;
    const __half* xl = back ? g_xl_b : g_xl_f;
    const float* al = back ? g_al_b : g_al_f;
    const float* ar = back ? g_ar_b : g_ar_f;
    const float* bias = back ? b_b : b_f;

    const int half = lane >> 4;   // which of 2 interleaved edge sequences
    const int sub = lane & 15;    // 16 lanes per edge, 8 halves each
    const int h = sub >> 2;       // head
    float arh = __ldg(&ar[n * 4 + h]);
    int beg = off[n];
    int end = (n == NN - 1) ? NEP : off[n + 1];

    float acc[8] = {0.f, 0.f, 0.f, 0.f, 0.f, 0.f, 0.f, 0.f};
    float den = 0.f;
    int j = beg + half;
    // 4 edges in flight per half: j, j+2, j+4, j+6; advance 8
    for (; j + 6 < end; j += 8) {
        int s0 = __ldg(&lst[j]);
        int s1 = __ldg(&lst[j + 2]);
        int s2 = __ldg(&lst[j + 4]);
        int s3 = __ldg(&lst[j + 6]);
        float a0 = __ldg(&al[s0 * 4 + h]);
        float a1 = __ldg(&al[s1 * 4 + h]);
        float a2 = __ldg(&al[s2 * 4 + h]);
        float a3 = __ldg(&al[s3 * 4 + h]);
        uint4 r0 = *(const uint4*)(xl + (size_t)s0 * HC + sub * 8);
        uint4 r1 = *(const uint4*)(xl + (size_t)s1 * HC + sub * 8);
        uint4 r2 = *(const uint4*)(xl + (size_t)s2 * HC + sub * 8);
        uint4 r3 = *(const uint4*)(xl + (size_t)s3 * HC + sub * 8);
        float w0 = __expf(lrelu(a0 + arh));
        float w1 = __expf(lrelu(a1 + arh));
        float w2 = __expf(lrelu(a2 + arh));
        float w3 = __expf(lrelu(a3 + arh));
        den += (w0 + w1) + (w2 + w3);
        float2 p;
        p = __half22float2(*(__half2*)&r0.x); acc[0] = fmaf(w0, p.x, acc[0]); acc[1] = fmaf(w0, p.y, acc[1]);
        p = __half22float2(*(__half2*)&r0.y); acc[2] = fmaf(w0, p.x, acc[2]); acc[3] = fmaf(w0, p.y, acc[3]);
        p = __half22float2(*(__half2*)&r0.z); acc[4] = fmaf(w0, p.x, acc[4]); acc[5] = fmaf(w0, p.y, acc[5]);
        p = __half22float2(*(__half2*)&r0.w); acc[6] = fmaf(w0, p.x, acc[6]); acc[7] = fmaf(w0, p.y, acc[7]);
        p = __half22float2(*(__half2*)&r1.x); acc[0] = fmaf(w1, p.x, acc[0]); acc[1] = fmaf(w1, p.y, acc[1]);
        p = __half22float2(*(__half2*)&r1.y); acc[2] = fmaf(w1, p.x, acc[2]); acc[3] = fmaf(w1, p.y, acc[3]);
        p = __half22float2(*(__half2*)&r1.z); acc[4] = fmaf(w1, p.x, acc[4]); acc[5] = fmaf(w1, p.y, acc[5]);
        p = __half22float2(*(__half2*)&r1.w); acc[6] = fmaf(w1, p.x, acc[6]); acc[7] = fmaf(w1, p.y, acc[7]);
        p = __half22float2(*(__half2*)&r2.x); acc[0] = fmaf(w2, p.x, acc[0]); acc[1] = fmaf(w2, p.y, acc[1]);
        p = __half22float2(*(__half2*)&r2.y); acc[2] = fmaf(w2, p.x, acc[2]); acc[3] = fmaf(w2, p.y, acc[3]);
        p = __half22float2(*(__half2*)&r2.z); acc[4] = fmaf(w2, p.x, acc[4]); acc[5] = fmaf(w2, p.y, acc[5]);
        p = __half22float2(*(__half2*)&r2.w); acc[6] = fmaf(w2, p.x, acc[6]); acc[7] = fmaf(w2, p.y, acc[7]);
        p = __half22float2(*(__half2*)&r3.x); acc[0] = fmaf(w3, p.x, acc[0]); acc[1] = fmaf(w3, p.y, acc[1]);
        p = __half22float2(*(__half2*)&r3.y); acc[2] = fmaf(w3, p.x, acc[2]); acc[3] = fmaf(w3, p.y, acc[3]);
        p = __half22float2(*(__half2*)&r3.z); acc[4] = fmaf(w3, p.x, acc[4]); acc[5] = fmaf(w3, p.y, acc[5]);
        p = __half22float2(*(__half2*)&r3.w); acc[6] = fmaf(w3, p.x, acc[6]); acc[7] = fmaf(w3, p.y, acc[7]);
    }
    for (; j < end; j += 2) {
        int s = __ldg(&lst[j]);
        float a = __ldg(&al[s * 4 + h]);
        uint4 r0 = *(const uint4*)(xl + (size_t)s * HC + sub * 8);
        float w = __expf(lrelu(a + arh));
        den += w;
        float2 p;
        p = __half22float2(*(__half2*)&r0.x); acc[0] = fmaf(w, p.x, acc[0]); acc[1] = fmaf(w, p.y, acc[1]);
        p = __half22float2(*(__half2*)&r0.y); acc[2] = fmaf(w, p.x, acc[2]); acc[3] = fmaf(w, p.y, acc[3]);
        p = __half22float2(*(__half2*)&r0.z); acc[4] = fmaf(w, p.x, acc[4]); acc[5] = fmaf(w, p.y, acc[5]);
        p = __half22float2(*(__half2*)&r0.w); acc[6] = fmaf(w, p.x, acc[6]); acc[7] = fmaf(w, p.y, acc[7]);
    }
    // combine the two halves
    den += __shfl_xor_sync(0xffffffffu, den, 16);
#pragma unroll
    for (int c = 0; c < 8; c++) acc[c] += __shfl_xor_sync(0xffffffffu, acc[c], 16);

    if (half == 0) {
        float inv = 1.f / (den + 1e-16f);
        float4 b0 = *(const float4*)(bias + sub * 8);
        float4 b1 = *(const float4*)(bias + sub * 8 + 4);
        float o0 = fmaf(acc[0], inv, b0.x), o1 = fmaf(acc[1], inv, b0.y);
        float o2 = fmaf(acc[2], inv, b0.z), o3 = fmaf(acc[3], inv, b0.w);
        float o4 = fmaf(acc[4], inv, b1.x), o5 = fmaf(acc[5], inv, b1.y);
        float o6 = fmaf(acc[6], inv, b1.z), o7 = fmaf(acc[7], inv, b1.w);
        __half2 h0 = __floats2half2_rn(o0, o1);
        __half2 h1 = __floats2half2_rn(o2, o3);
        __half2 h2 = __floats2half2_rn(o4, o5);
        __half2 h3 = __floats2half2_rn(o6, o7);
        *(uint4*)(g_agg_h + (size_t)n * 256 + (back ? 128 : 0) + sub * 8) =
            make_uint4(*(unsigned*)&h0, *(unsigned*)&h1,
                       *(unsigned*)&h2, *(unsigned*)&h3);
    }
}

// ---------------- launch ----------------
extern "C" void kernel_launch(void* const* d_in, const int* in_sizes, int n_in,
                              void* d_out, int out_size) {
    const float* x        = (const float*)d_in[0];
    const int*   ei       = (const int*)d_in[1];
    const float* W_f      = (const float*)d_in[2];
    const float* a_src_f  = (const float*)d_in[3];
    const float* a_dst_f  = (const float*)d_in[4];
    const float* b_f      = (const float*)d_in[5];
    const float* W_b      = (const float*)d_in[6];
    const float* a_src_b  = (const float*)d_in[7];
    const float* a_dst_b  = (const float*)d_in[8];
    const float* b_b      = (const float*)d_in[9];
    const float* W_fuse   = (const float*)d_in[10];
    const float* b_fuse   = (const float*)d_in[11];
    const float* gamma    = (const float*)d_in[12];
    const float* beta     = (const float*)d_in[13];
    const float* run_mean = (const float*)d_in[14];
    const float* run_var  = (const float*)d_in[15];
    float* out = (float*)d_out;

    static cudaStream_t s_side = nullptr;
    static cudaEvent_t ev_fork = nullptr, ev_join = nullptr;
    if (!s_side) {
        cudaStreamCreateWithFlags(&s_side, cudaStreamNonBlocking);
        cudaEventCreateWithFlags(&ev_fork, cudaEventDisableTiming);
        cudaEventCreateWithFlags(&ev_join, cudaEventDisableTiming);
        cudaFuncSetAttribute(hgemm_kernel<0>, cudaFuncAttributeMaxDynamicSharedMemorySize, SMEM_SZ);
        cudaFuncSetAttribute(hgemm_kernel<1>, cudaFuncAttributeMaxDynamicSharedMemorySize, SMEM_SZ);
    }

    cudaEventRecord(ev_fork, 0);
    cudaStreamWaitEvent(s_side, ev_fork, 0);

    // side stream: CSR build (depends only on edge_index)
    pack_kernel<<<(NN + 255) / 256, 256, 0, s_side>>>(b_fuse, gamma, beta, run_mean, run_var);
    hist_kernel<<<(NEP / 4 + 255) / 256, 256, 0, s_side>>>(ei);
    scan_kernel<<<2, 1024, 0, s_side>>>();
    scatter_kernel<<<(NEP + 255) / 256, 256, 0, s_side>>>(ei);
    cudaEventRecord(ev_join, s_side);

    // main stream
    conv_w_kernel<<<(KDIM * 256 + 255) / 256, 256>>>(W_f, W_b, W_fuse);
    conv_x_kernel<<<(NN * KDIM / 8 + 255) / 256, 256>>>(x);

    dim3 gg((NN + 127) / 128, 2);
    hgemm_kernel<0><<<gg, 256, SMEM_SZ>>>(nullptr, a_src_f, a_dst_f, a_src_b, a_dst_b);

    cudaStreamWaitEvent(0, ev_join, 0);
    gather_kernel<<<(2 * NN * 32 + 255) / 256, 256>>>(b_f, b_b);

    hgemm_kernel<1><<<gg, 256, SMEM_SZ>>>(out, nullptr, nullptr, nullptr, nullptr);
}